// round 10
// baseline (speedup 1.0000x reference)
#include <cuda_runtime.h>
#include <math.h>

#define Bn 4
#define Dn 64
#define Hn 64
#define Wn 64
#define CHn 150
#define PLANE 4096
#define VOL   262144
#define VOX   1048576

typedef unsigned long long ull;

__device__ float g_p[VOX];
__device__ float g_c[VOX];   // r * (1 - p)
__device__ float g_v[VOX];   // ping-pong buffer

// ---------------- packed f32x2 helpers (sm_103a) ----------------
__device__ __forceinline__ ull pk2(float a, float b) {
    ull r; asm("mov.b64 %0, {%1, %2};" : "=l"(r) : "f"(a), "f"(b)); return r;
}
__device__ __forceinline__ void upk2(ull v, float& a, float& b) {
    asm("mov.b64 {%0, %1}, %2;" : "=f"(a), "=f"(b) : "l"(v));
}
__device__ __forceinline__ ull fma2(ull a, ull b, ull c) {
    ull d; asm("fma.rn.f32x2 %0, %1, %2, %3;" : "=l"(d) : "l"(a), "l"(b), "l"(c));
    return d;
}
__device__ __forceinline__ float4 max4(float4 a, float4 b) {
    return make_float4(fmaxf(a.x, b.x), fmaxf(a.y, b.y),
                       fmaxf(a.z, b.z), fmaxf(a.w, b.w));
}

// ---------------------------------------------------------------------------
// Kernel 1: p = sigmoid(sum_c pw[c]*relu(conv3x3x3_c(x)+b[c]))
//           writes g_p, g_c = r*(1-p), v0 = r into vout.
// DCH=1: 1024 blocks (64,4,4) -> ~4 co-resident/SM, dynamic scheduling
// removes the 1.18x wave-quantization tax of the 256-block version.
// ---------------------------------------------------------------------------
#define HT  16
#define XROW 68
#define XHL 18
#define XDL 3
#define NPAIR 75

__global__ __launch_bounds__(256) void compute_p_kernel(
    const float* __restrict__ image, const float* __restrict__ hw,
    const float* __restrict__ hb,    const float* __restrict__ pw,
    float* __restrict__ vout)
{
    __shared__ float  xs[XDL * XHL * XROW];   // 14688 B
    __shared__ float4 ws4[NPAIR * 28];        // 33600 B
    __shared__ float4 bp4[NPAIR];
    __shared__ float4 pp4[NPAIR];

    const int tid = threadIdx.x;

    for (int i = tid; i < NPAIR * 27; i += 256) {
        const int pr = i / 27, t = i % 27;
        const float wA = hw[(pr * 2) * 27 + t];
        const float wB = hw[(pr * 2 + 1) * 27 + t];
        ws4[pr * 28 + t] = make_float4(wA, wA, wB, wB);
    }
    for (int i = tid; i < NPAIR; i += 256) {
        const float bA = hb[i * 2], bB = hb[i * 2 + 1];
        const float pA = pw[i * 2], pB = pw[i * 2 + 1];
        bp4[i] = make_float4(bA, bA, bB, bB);
        pp4[i] = make_float4(pA, pA, pB, pB);
    }

    const int d0 = blockIdx.x;                // one d-slice per block
    const int h0 = blockIdx.y * HT;
    const int b  = blockIdx.z;
    const float* xg = image + (size_t)b * 2 * VOL;
    const float* rg = xg + VOL;

    for (int i = tid; i < XDL * XHL * 66; i += 256) {
        int wl = i % 66; int rest = i / 66;
        int hl = rest % XHL; int dl = rest / XHL;
        int gw = wl - 1, gh = h0 + hl - 1, gd = d0 + dl - 1;
        float v = 0.0f;
        if (gw >= 0 && gw < Wn && gh >= 0 && gh < Hn && gd >= 0 && gd < Dn)
            v = xg[((size_t)gd * Hn + gh) * Wn + gw];
        xs[(dl * XHL + hl) * XROW + wl] = v;
    }
    __syncthreads();

    const int wt = tid & 15;
    const int ht = tid >> 4;
    const int w0 = wt * 4;

    {
        ull P[9][5];
        #pragma unroll
        for (int r9 = 0; r9 < 9; r9++) {
            const int dz = r9 / 3, hy = r9 % 3;
            const float* base = &xs[(dz * XHL + (ht + hy)) * XROW + w0];
            float4 a  = *(const float4*)base;
            float2 b2 = *(const float2*)(base + 4);
            P[r9][0] = pk2(a.x, a.y);
            P[r9][1] = pk2(a.y, a.z);
            P[r9][2] = pk2(a.z, a.w);
            P[r9][3] = pk2(a.w, b2.x);
            P[r9][4] = pk2(b2.x, b2.y);
        }

        ull z01 = 0ull, z23 = 0ull;

        #pragma unroll 1
        for (int cp = 0; cp < NPAIR; cp++) {
            const ulonglong2* wp = (const ulonglong2*)(ws4 + cp * 28);
            const ulonglong2 bb = ((const ulonglong2*)bp4)[cp];
            ull aA01 = bb.x, aA23 = bb.x;
            ull aB01 = bb.y, aB23 = bb.y;
            #pragma unroll
            for (int t = 0; t < 27; t++) {
                const ulonglong2 w2 = wp[t];
                const int r9 = t / 3, kx = t % 3;
                aA01 = fma2(w2.x, P[r9][kx],     aA01);
                aA23 = fma2(w2.x, P[r9][kx + 2], aA23);
                aB01 = fma2(w2.y, P[r9][kx],     aB01);
                aB23 = fma2(w2.y, P[r9][kx + 2], aB23);
            }
            float a0, a1, a2, a3, b0, b1, b2, b3;
            upk2(aA01, a0, a1); upk2(aA23, a2, a3);
            upk2(aB01, b0, b1); upk2(aB23, b2, b3);
            a0 = fmaxf(a0, 0.f); a1 = fmaxf(a1, 0.f);
            a2 = fmaxf(a2, 0.f); a3 = fmaxf(a3, 0.f);
            b0 = fmaxf(b0, 0.f); b1 = fmaxf(b1, 0.f);
            b2 = fmaxf(b2, 0.f); b3 = fmaxf(b3, 0.f);
            const ulonglong2 pv = ((const ulonglong2*)pp4)[cp];
            z01 = fma2(pv.x, pk2(a0, a1), z01);
            z23 = fma2(pv.x, pk2(a2, a3), z23);
            z01 = fma2(pv.y, pk2(b0, b1), z01);
            z23 = fma2(pv.y, pk2(b2, b3), z23);
        }

        float z0, z1, z2, z3;
        upk2(z01, z0, z1); upk2(z23, z2, z3);

        const int gd = d0, gh = h0 + ht;
        const size_t o = ((size_t)b * Dn + gd) * PLANE + gh * Wn + w0;
        const float4 r4 = *(const float4*)&rg[((size_t)gd * Hn + gh) * Wn + w0];

        const float p0 = 1.f / (1.f + __expf(-z0));
        const float p1 = 1.f / (1.f + __expf(-z1));
        const float p2 = 1.f / (1.f + __expf(-z2));
        const float p3 = 1.f / (1.f + __expf(-z3));

        *(float4*)&g_p[o]  = make_float4(p0, p1, p2, p3);
        *(float4*)&g_c[o]  = make_float4(r4.x * (1.f - p0), r4.y * (1.f - p1),
                                         r4.z * (1.f - p2), r4.w * (1.f - p3));
        *(float4*)&vout[o] = r4;
    }
}

// ---------------------------------------------------------------------------
// Kernel 2: one propagation iteration.  Block = 16-row slice of (b,d) plane.
// 1024 blocks, ~6 CTAs/SM; all independent global loads issued up front.
// ---------------------------------------------------------------------------
__global__ __launch_bounds__(256) void iter_kernel(
    const float4* __restrict__ vin, float4* __restrict__ vout,
    const int* __restrict__ kptr, int it)
{
    __shared__ float4 vz[18 * 16];    // d-max, rows h0-1 .. h0+16 (clamped)

    const int blk = blockIdx.x;
    const int bd  = blk >> 2;         // b*64 + d
    const int h0  = (blk & 3) * 16;
    const int d   = bd & 63;
    const int tid = threadIdx.x;
    const bool skip = (it >= *kptr);

    const size_t base = (size_t)bd * 1024;
    const long long dm = (d > 0)  ? -1024 : 0;
    const long long dp = (d < 63) ?  1024 : 0;

    const int ro = tid >> 4;          // 0..15
    const int c4 = tid & 15;
    const size_t off = base + (h0 + ro) * 16 + c4;

    // ---- issue ALL independent loads up front ----
    const float4 cen = vin[off];
    const float4 vm  = vin[off + dm];
    const float4 vp  = vin[off + dp];
    const float4 pp  = ((const float4*)g_p)[off];
    const float4 cc  = ((const float4*)g_c)[off];

    float4 hcen, hdm, hdp;
    int hrow = 0;
    if (tid < 32) {                   // halo rows h0-1 and h0+16
        const int hc4 = tid & 15;
        const int hr  = (tid < 16) ? -1 : 16;
        const int gh  = min(63, max(0, h0 + hr));
        const size_t hoff = base + gh * 16 + hc4;
        hcen = vin[hoff];
        hdm  = vin[hoff + dm];
        hdp  = vin[hoff + dp];
        hrow = (hr + 1) * 16 + hc4;   // row 0 or 17
    }

    // ---- stage 1: d-max into SMEM ----
    vz[(ro + 1) * 16 + c4] = max4(max4(cen, vm), vp);
    if (tid < 32)
        vz[hrow] = max4(max4(hcen, hdm), hdp);
    __syncthreads();

    // ---- stage 2: h-max + w-max + update ----
    float4 hm = max4(max4(vz[ro * 16 + c4], vz[(ro + 1) * 16 + c4]),
                     vz[(ro + 2) * 16 + c4]);

    float lf = __shfl_up_sync(0xffffffffu, hm.w, 1);
    float rt = __shfl_down_sync(0xffffffffu, hm.x, 1);
    if (c4 == 0)  lf = hm.x;          // w==0 edge (also fixes row crossing)
    if (c4 == 15) rt = hm.w;          // w==63 edge

    float4 m;
    m.x = fmaxf(lf,   fmaxf(hm.x, hm.y));
    m.y = fmaxf(hm.x, fmaxf(hm.y, hm.z));
    m.z = fmaxf(hm.y, fmaxf(hm.z, hm.w));
    m.w = fmaxf(hm.z, fmaxf(hm.w, rt));

    float4 nv;
    nv.x = fmaxf(cen.x, fmaf(pp.x, m.x, cc.x));
    nv.y = fmaxf(cen.y, fmaf(pp.y, m.y, cc.y));
    nv.z = fmaxf(cen.z, fmaf(pp.z, m.z, cc.z));
    nv.w = fmaxf(cen.w, fmaf(pp.w, m.w, cc.w));

    vout[off] = skip ? cen : nv;
}

// ---------------------------------------------------------------------------
extern "C" void kernel_launch(void* const* d_in, const int* in_sizes, int n_in,
                              void* d_out, int out_size)
{
    const float* image = (const float*)d_in[0];
    const float* hw    = (const float*)d_in[1];
    const float* hb    = (const float*)d_in[2];
    const float* pw    = (const float*)d_in[3];
    const int*   kptr  = (const int*)d_in[4];
    float* out = (float*)d_out;

    void* pv = nullptr;
    cudaGetSymbolAddress(&pv, g_v);
    float* vbuf = (float*)pv;

    compute_p_kernel<<<dim3(64, 4, 4), 256>>>(image, hw, hb, pw, out);

    const float* src = out;
    float* dst = vbuf;
    for (int i = 0; i < 30; i++) {
        iter_kernel<<<Bn * Dn * 4, 256>>>((const float4*)src, (float4*)dst, kptr, i);
        float* t = dst; dst = (float*)src; src = t;
    }
    // 30 iterations (even count): final write lands in d_out.
}

// round 11
// speedup vs baseline: 1.0704x; 1.0704x over previous
#include <cuda_runtime.h>
#include <math.h>

#define Bn 4
#define Dn 64
#define Hn 64
#define Wn 64
#define CHn 150
#define PLANE 4096
#define VOL   262144
#define VOX   1048576

typedef unsigned long long ull;

__device__ float g_p[VOX];
__device__ float g_c[VOX];   // r * (1 - p)
__device__ float g_v[VOX];   // ping-pong buffer

// ---------------- packed f32x2 helpers (sm_103a) ----------------
__device__ __forceinline__ ull pk2(float a, float b) {
    ull r; asm("mov.b64 %0, {%1, %2};" : "=l"(r) : "f"(a), "f"(b)); return r;
}
__device__ __forceinline__ void upk2(ull v, float& a, float& b) {
    asm("mov.b64 {%0, %1}, %2;" : "=f"(a), "=f"(b) : "l"(v));
}
__device__ __forceinline__ ull fma2(ull a, ull b, ull c) {
    ull d; asm("fma.rn.f32x2 %0, %1, %2, %3;" : "=l"(d) : "l"(a), "l"(b), "l"(c));
    return d;
}
__device__ __forceinline__ float4 max4(float4 a, float4 b) {
    return make_float4(fmaxf(a.x, b.x), fmaxf(a.y, b.y),
                       fmaxf(a.z, b.z), fmaxf(a.w, b.w));
}

// ---------------------------------------------------------------------------
// Kernel 1 (R10 winner): p = sigmoid(sum_c pw[c]*relu(conv3x3x3_c(x)+b[c]))
// DCH=1, 1024 blocks (64,4,4): no wave-quantization tax.  ~106 us.
// ---------------------------------------------------------------------------
#define HT  16
#define XROW 68
#define XHL 18
#define XDL 3
#define NPAIR 75

__global__ __launch_bounds__(256) void compute_p_kernel(
    const float* __restrict__ image, const float* __restrict__ hw,
    const float* __restrict__ hb,    const float* __restrict__ pw,
    float* __restrict__ vout)
{
    __shared__ float  xs[XDL * XHL * XROW];   // 14688 B
    __shared__ float4 ws4[NPAIR * 28];        // 33600 B
    __shared__ float4 bp4[NPAIR];
    __shared__ float4 pp4[NPAIR];

    const int tid = threadIdx.x;

    for (int i = tid; i < NPAIR * 27; i += 256) {
        const int pr = i / 27, t = i % 27;
        const float wA = hw[(pr * 2) * 27 + t];
        const float wB = hw[(pr * 2 + 1) * 27 + t];
        ws4[pr * 28 + t] = make_float4(wA, wA, wB, wB);
    }
    for (int i = tid; i < NPAIR; i += 256) {
        const float bA = hb[i * 2], bB = hb[i * 2 + 1];
        const float pA = pw[i * 2], pB = pw[i * 2 + 1];
        bp4[i] = make_float4(bA, bA, bB, bB);
        pp4[i] = make_float4(pA, pA, pB, pB);
    }

    const int d0 = blockIdx.x;                // one d-slice per block
    const int h0 = blockIdx.y * HT;
    const int b  = blockIdx.z;
    const float* xg = image + (size_t)b * 2 * VOL;
    const float* rg = xg + VOL;

    for (int i = tid; i < XDL * XHL * 66; i += 256) {
        int wl = i % 66; int rest = i / 66;
        int hl = rest % XHL; int dl = rest / XHL;
        int gw = wl - 1, gh = h0 + hl - 1, gd = d0 + dl - 1;
        float v = 0.0f;
        if (gw >= 0 && gw < Wn && gh >= 0 && gh < Hn && gd >= 0 && gd < Dn)
            v = xg[((size_t)gd * Hn + gh) * Wn + gw];
        xs[(dl * XHL + hl) * XROW + wl] = v;
    }
    __syncthreads();

    const int wt = tid & 15;
    const int ht = tid >> 4;
    const int w0 = wt * 4;

    {
        ull P[9][5];
        #pragma unroll
        for (int r9 = 0; r9 < 9; r9++) {
            const int dz = r9 / 3, hy = r9 % 3;
            const float* base = &xs[(dz * XHL + (ht + hy)) * XROW + w0];
            float4 a  = *(const float4*)base;
            float2 b2 = *(const float2*)(base + 4);
            P[r9][0] = pk2(a.x, a.y);
            P[r9][1] = pk2(a.y, a.z);
            P[r9][2] = pk2(a.z, a.w);
            P[r9][3] = pk2(a.w, b2.x);
            P[r9][4] = pk2(b2.x, b2.y);
        }

        ull z01 = 0ull, z23 = 0ull;

        #pragma unroll 1
        for (int cp = 0; cp < NPAIR; cp++) {
            const ulonglong2* wp = (const ulonglong2*)(ws4 + cp * 28);
            const ulonglong2 bb = ((const ulonglong2*)bp4)[cp];
            ull aA01 = bb.x, aA23 = bb.x;
            ull aB01 = bb.y, aB23 = bb.y;
            #pragma unroll
            for (int t = 0; t < 27; t++) {
                const ulonglong2 w2 = wp[t];
                const int r9 = t / 3, kx = t % 3;
                aA01 = fma2(w2.x, P[r9][kx],     aA01);
                aA23 = fma2(w2.x, P[r9][kx + 2], aA23);
                aB01 = fma2(w2.y, P[r9][kx],     aB01);
                aB23 = fma2(w2.y, P[r9][kx + 2], aB23);
            }
            float a0, a1, a2, a3, b0, b1, b2, b3;
            upk2(aA01, a0, a1); upk2(aA23, a2, a3);
            upk2(aB01, b0, b1); upk2(aB23, b2, b3);
            a0 = fmaxf(a0, 0.f); a1 = fmaxf(a1, 0.f);
            a2 = fmaxf(a2, 0.f); a3 = fmaxf(a3, 0.f);
            b0 = fmaxf(b0, 0.f); b1 = fmaxf(b1, 0.f);
            b2 = fmaxf(b2, 0.f); b3 = fmaxf(b3, 0.f);
            const ulonglong2 pv = ((const ulonglong2*)pp4)[cp];
            z01 = fma2(pv.x, pk2(a0, a1), z01);
            z23 = fma2(pv.x, pk2(a2, a3), z23);
            z01 = fma2(pv.y, pk2(b0, b1), z01);
            z23 = fma2(pv.y, pk2(b2, b3), z23);
        }

        float z0, z1, z2, z3;
        upk2(z01, z0, z1); upk2(z23, z2, z3);

        const int gd = d0, gh = h0 + ht;
        const size_t o = ((size_t)b * Dn + gd) * PLANE + gh * Wn + w0;
        const float4 r4 = *(const float4*)&rg[((size_t)gd * Hn + gh) * Wn + w0];

        const float p0 = 1.f / (1.f + __expf(-z0));
        const float p1 = 1.f / (1.f + __expf(-z1));
        const float p2 = 1.f / (1.f + __expf(-z2));
        const float p3 = 1.f / (1.f + __expf(-z3));

        *(float4*)&g_p[o]  = make_float4(p0, p1, p2, p3);
        *(float4*)&g_c[o]  = make_float4(r4.x * (1.f - p0), r4.y * (1.f - p1),
                                         r4.z * (1.f - p2), r4.w * (1.f - p3));
        *(float4*)&vout[o] = r4;
    }
}

// ---------------------------------------------------------------------------
// Kernel 2 (R9 winner): one propagation iteration.
// Block = 32-row half-plane of (b,d); 512 blocks; ALL independent global
// loads issued up front (MLP ~13/thread).  ~6.2 us/launch.
// ---------------------------------------------------------------------------
__global__ __launch_bounds__(256) void iter_kernel(
    const float4* __restrict__ vin, float4* __restrict__ vout,
    const int* __restrict__ kptr, int it)
{
    __shared__ float4 vz[34 * 16];    // d-max, rows h0-1 .. h0+32 (clamped)

    const int blk = blockIdx.x;
    const int bd  = blk >> 1;         // b*64 + d
    const int h0  = (blk & 1) * 32;
    const int d   = bd & 63;
    const int tid = threadIdx.x;
    const bool skip = (it >= *kptr);

    const size_t base = (size_t)bd * 1024;
    const long long dm = (d > 0)  ? -1024 : 0;
    const long long dp = (d < 63) ?  1024 : 0;

    const int ro0 = tid >> 4;         // 0..15  (q=0 row)
    const int c4  = tid & 15;
    const size_t off0 = base + (h0 + ro0) * 16 + c4;
    const size_t off1 = off0 + 16 * 16;                 // q=1 row (+16 rows)

    // ---- issue ALL independent loads up front ----
    float4 cen0 = vin[off0],      cen1 = vin[off1];
    float4 vm0  = vin[off0 + dm], vm1  = vin[off1 + dm];
    float4 vp0  = vin[off0 + dp], vp1  = vin[off1 + dp];
    const float4 pp0 = ((const float4*)g_p)[off0];
    const float4 pp1 = ((const float4*)g_p)[off1];
    const float4 cc0 = ((const float4*)g_c)[off0];
    const float4 cc1 = ((const float4*)g_c)[off1];

    float4 hcen, hdm, hdp;
    int hrow = 0;
    if (tid < 32) {                   // halo rows h0-1 and h0+32
        const int hc4 = tid & 15;
        const int hr  = (tid < 16) ? -1 : 32;
        const int gh  = min(63, max(0, h0 + hr));
        const size_t hoff = base + gh * 16 + hc4;
        hcen = vin[hoff];
        hdm  = vin[hoff + dm];
        hdp  = vin[hoff + dp];
        hrow = (hr + 1) * 16 + hc4;   // row 0 or 33
    }

    // ---- stage 1: d-max into SMEM ----
    vz[(ro0 + 1) * 16 + c4]      = max4(max4(cen0, vm0), vp0);
    vz[(ro0 + 1 + 16) * 16 + c4] = max4(max4(cen1, vm1), vp1);
    if (tid < 32)
        vz[hrow] = max4(max4(hcen, hdm), hdp);
    __syncthreads();

    // ---- stage 2: h-max + w-max + update ----
    #pragma unroll
    for (int q = 0; q < 2; q++) {
        const int ro = ro0 + q * 16;

        float4 hm = max4(max4(vz[ro * 16 + c4], vz[(ro + 1) * 16 + c4]),
                         vz[(ro + 2) * 16 + c4]);

        float lf = __shfl_up_sync(0xffffffffu, hm.w, 1);
        float rt = __shfl_down_sync(0xffffffffu, hm.x, 1);
        if (c4 == 0)  lf = hm.x;      // w==0 edge (also fixes row crossing)
        if (c4 == 15) rt = hm.w;      // w==63 edge

        float4 m;
        m.x = fmaxf(lf,   fmaxf(hm.x, hm.y));
        m.y = fmaxf(hm.x, fmaxf(hm.y, hm.z));
        m.z = fmaxf(hm.y, fmaxf(hm.z, hm.w));
        m.w = fmaxf(hm.z, fmaxf(hm.w, rt));

        const float4 cen = q ? cen1 : cen0;
        const float4 pp  = q ? pp1  : pp0;
        const float4 cc  = q ? cc1  : cc0;

        float4 nv;
        nv.x = fmaxf(cen.x, fmaf(pp.x, m.x, cc.x));
        nv.y = fmaxf(cen.y, fmaf(pp.y, m.y, cc.y));
        nv.z = fmaxf(cen.z, fmaf(pp.z, m.z, cc.z));
        nv.w = fmaxf(cen.w, fmaf(pp.w, m.w, cc.w));

        vout[q ? off1 : off0] = skip ? cen : nv;
    }
}

// ---------------------------------------------------------------------------
extern "C" void kernel_launch(void* const* d_in, const int* in_sizes, int n_in,
                              void* d_out, int out_size)
{
    const float* image = (const float*)d_in[0];
    const float* hw    = (const float*)d_in[1];
    const float* hb    = (const float*)d_in[2];
    const float* pw    = (const float*)d_in[3];
    const int*   kptr  = (const int*)d_in[4];
    float* out = (float*)d_out;

    void* pv = nullptr;
    cudaGetSymbolAddress(&pv, g_v);
    float* vbuf = (float*)pv;

    compute_p_kernel<<<dim3(64, 4, 4), 256>>>(image, hw, hb, pw, out);

    const float* src = out;
    float* dst = vbuf;
    for (int i = 0; i < 30; i++) {
        iter_kernel<<<Bn * Dn * 2, 256>>>((const float4*)src, (float4*)dst, kptr, i);
        float* t = dst; dst = (float*)src; src = t;
    }
    // 30 iterations (even count): final write lands in d_out.
}

// round 14
// speedup vs baseline: 1.1797x; 1.1022x over previous
#include <cuda_runtime.h>
#include <math.h>
#include <stdint.h>

#define Bn 4
#define Dn 64
#define Hn 64
#define Wn 64
#define PLANE 4096
#define VOL   262144
#define VOX   1048576

typedef unsigned long long ull;

__device__ float g_p[VOX];
__device__ float g_c[VOX];   // r * (1 - p)
__device__ float g_v[VOX];   // ping-pong buffer

// ---------------- helpers ----------------
__device__ __forceinline__ float4 max4(float4 a, float4 b) {
    return make_float4(fmaxf(a.x, b.x), fmaxf(a.y, b.y),
                       fmaxf(a.z, b.z), fmaxf(a.w, b.w));
}
__device__ __forceinline__ uint32_t cvt_tf32(float x) {
    uint32_t r; asm("cvt.rna.tf32.f32 %0, %1;" : "=r"(r) : "f"(x)); return r;
}
// warp-level tf32 MMA (base ISA, compiles for sm_103)
__device__ __forceinline__ void mma_tf32(float& c0, float& c1, float& c2, float& c3,
                                         const uint32_t a[4], const uint32_t b[2]) {
    asm volatile(
        "mma.sync.aligned.m16n8k8.row.col.f32.tf32.tf32.f32 "
        "{%0,%1,%2,%3}, {%4,%5,%6,%7}, {%8,%9}, {%0,%1,%2,%3};"
        : "+f"(c0), "+f"(c1), "+f"(c2), "+f"(c3)
        : "r"(a[0]), "r"(a[1]), "r"(a[2]), "r"(a[3]), "r"(b[0]), "r"(b[1]));
}

// ---------------------------------------------------------------------------
// Kernel 1: tf32 mma.sync implicit-GEMM conv.
// Block = 256 thr (8 warps) = one d-slice x 8 h-rows; warp = one h-row (64 w)
// = 4 M-tiles of 16.  D[pos,ch] = A[pos,K32] @ W[ch,K32]^T; K=27,ch=150 padded.
// A-fragments gathered straight from the xs halo tile (no im2col matrix).
// Epilogue: z = sum pw*relu(d+b); p = sigmoid(z); writes g_p, g_c, v0.
// ---------------------------------------------------------------------------
#define XH  10
#define XRW 68
#define BSTR 17   // B row stride in float2 (16 used + 1 pad)

__global__ __launch_bounds__(256) void conv_mma_kernel(
    const float* __restrict__ image, const float* __restrict__ hw,
    const float* __restrict__ hb,    const float* __restrict__ pw,
    float* __restrict__ vout)
{
    __shared__ float  xs[3 * XH * XRW];     // 8160 B
    __shared__ float2 B2[160 * BSTR];       // 21760 B: (tap, tap+4) tf32 pairs
    __shared__ float2 wb[160];              // (pw, hb)

    const int tid  = threadIdx.x;
    const int warp = tid >> 5;
    const int lane = tid & 31;
    const int d0 = blockIdx.x;
    const int h0 = blockIdx.y * 8;
    const int b  = blockIdx.z;

    // ---- weights: B2[ch][kk*4+j] = tf32(w[ch][kk*8+j], w[ch][kk*8+j+4]) ----
    for (int i = tid; i < 160 * 16; i += 256) {
        const int ch = i >> 4, kp = i & 15;
        const int kk = kp >> 2, j = kp & 3;
        const int t0 = kk * 8 + j, t1 = t0 + 4;
        const float w0 = (ch < 150 && t0 < 27) ? hw[ch * 27 + t0] : 0.f;
        const float w1 = (ch < 150 && t1 < 27) ? hw[ch * 27 + t1] : 0.f;
        B2[ch * BSTR + kp] = make_float2(__uint_as_float(cvt_tf32(w0)),
                                         __uint_as_float(cvt_tf32(w1)));
    }
    for (int i = tid; i < 160; i += 256)
        wb[i] = (i < 150) ? make_float2(pw[i], hb[i]) : make_float2(0.f, 0.f);

    // ---- x halo tile: planes d0-1..d0+1, rows h0-1..h0+8, cols -1..64 ----
    const float* xg = image + (size_t)b * 2 * VOL;
    const float* rg = xg + VOL;
    for (int i = tid; i < 3 * XH * 66; i += 256) {
        const int wl = i % 66; const int rest = i / 66;
        const int rl = rest % XH; const int dz = rest / XH;
        const int gw = wl - 1, gh = h0 + rl - 1, gd = d0 + dz - 1;
        float v = 0.f;
        if (gw >= 0 && gw < Wn && gh >= 0 && gh < Hn && gd >= 0 && gd < Dn)
            v = xg[((size_t)gd * Hn + gh) * Wn + gw];
        xs[(dz * XH + rl) * XRW + wl] = v;
    }
    __syncthreads();

    const int g   = lane >> 2;     // 0..7
    const int tig = lane & 3;      // 0..3
    const int hl  = warp;          // this warp's h row

    #pragma unroll 1
    for (int mt = 0; mt < 4; mt++) {
        // ---- gather A fragments for all 4 k-steps (16 regs) ----
        uint32_t afr[4][4];
        #pragma unroll
        for (int kk = 0; kk < 4; kk++) {
            #pragma unroll
            for (int hh = 0; hh < 2; hh++) {        // hh=0: a0,a1; hh=1: a2,a3
                const int t = kk * 8 + tig + hh * 4;
                uint32_t lo = 0u, hi = 0u;
                if (t < 27) {
                    const int dz = t / 9, rem = t - dz * 9;
                    const int hy = rem / 3, kx = rem - hy * 3;
                    const float* rp = &xs[(dz * XH + hl + hy) * XRW + mt * 16 + g + kx];
                    lo = cvt_tf32(rp[0]);           // A row g
                    hi = cvt_tf32(rp[8]);           // A row g+8
                }
                afr[kk][hh * 2 + 0] = lo;
                afr[kk][hh * 2 + 1] = hi;
            }
        }

        float z0 = 0.f, z1 = 0.f;

        #pragma unroll 1
        for (int nt = 0; nt < 20; nt++) {
            // B fragments: ch = nt*8 + g
            uint32_t bfr[4][2];
            const float2* bp = &B2[(nt * 8 + g) * BSTR + tig];
            #pragma unroll
            for (int kk = 0; kk < 4; kk++) {
                const float2 bb = bp[kk * 4];
                bfr[kk][0] = __float_as_uint(bb.x);
                bfr[kk][1] = __float_as_uint(bb.y);
            }
            float c0 = 0.f, c1 = 0.f, c2 = 0.f, c3 = 0.f;
            #pragma unroll
            for (int kk = 0; kk < 4; kk++)
                mma_tf32(c0, c1, c2, c3, afr[kk], bfr[kk]);

            // epilogue fold: cols nt*8 + 2*tig, +1
            const float4 wq = *(const float4*)&wb[nt * 8 + 2 * tig]; // pw0,b0,pw1,b1
            z0 = fmaf(wq.x, fmaxf(c0 + wq.y, 0.f),
                 fmaf(wq.z, fmaxf(c1 + wq.w, 0.f), z0));
            z1 = fmaf(wq.x, fmaxf(c2 + wq.y, 0.f),
                 fmaf(wq.z, fmaxf(c3 + wq.w, 0.f), z1));
        }

        // quad reduction over the 4 lanes holding this row's 8 cols
        z0 += __shfl_xor_sync(0xffffffffu, z0, 1);
        z0 += __shfl_xor_sync(0xffffffffu, z0, 2);
        z1 += __shfl_xor_sync(0xffffffffu, z1, 1);
        z1 += __shfl_xor_sync(0xffffffffu, z1, 2);

        if (tig < 2) {
            const int w  = mt * 16 + g + (tig == 1 ? 8 : 0);
            const float z = (tig == 1) ? z1 : z0;
            const int gh = h0 + hl;
            const size_t o = ((size_t)b * Dn + d0) * PLANE + gh * Wn + w;
            const float r = rg[((size_t)d0 * Hn + gh) * Wn + w];
            const float p = 1.f / (1.f + __expf(-z));
            g_p[o]  = p;
            g_c[o]  = r * (1.f - p);
            vout[o] = r;
        }
    }
}

// ---------------------------------------------------------------------------
// Kernel 2 (proven R11): one propagation iteration, 32-row half-planes,
// all independent global loads issued up front.
// ---------------------------------------------------------------------------
__global__ __launch_bounds__(256) void iter_kernel(
    const float4* __restrict__ vin, float4* __restrict__ vout,
    const int* __restrict__ kptr, int it)
{
    __shared__ float4 vz[34 * 16];

    const int blk = blockIdx.x;
    const int bd  = blk >> 1;
    const int h0  = (blk & 1) * 32;
    const int d   = bd & 63;
    const int tid = threadIdx.x;
    const bool skip = (it >= *kptr);

    const size_t base = (size_t)bd * 1024;
    const long long dm = (d > 0)  ? -1024 : 0;
    const long long dp = (d < 63) ?  1024 : 0;

    const int ro0 = tid >> 4;
    const int c4  = tid & 15;
    const size_t off0 = base + (h0 + ro0) * 16 + c4;
    const size_t off1 = off0 + 16 * 16;

    float4 cen0 = vin[off0],      cen1 = vin[off1];
    float4 vm0  = vin[off0 + dm], vm1  = vin[off1 + dm];
    float4 vp0  = vin[off0 + dp], vp1  = vin[off1 + dp];
    const float4 pp0 = ((const float4*)g_p)[off0];
    const float4 pp1 = ((const float4*)g_p)[off1];
    const float4 cc0 = ((const float4*)g_c)[off0];
    const float4 cc1 = ((const float4*)g_c)[off1];

    float4 hcen, hdm, hdp;
    int hrow = 0;
    if (tid < 32) {
        const int hc4 = tid & 15;
        const int hr  = (tid < 16) ? -1 : 32;
        const int gh  = min(63, max(0, h0 + hr));
        const size_t hoff = base + gh * 16 + hc4;
        hcen = vin[hoff];
        hdm  = vin[hoff + dm];
        hdp  = vin[hoff + dp];
        hrow = (hr + 1) * 16 + hc4;
    }

    vz[(ro0 + 1) * 16 + c4]      = max4(max4(cen0, vm0), vp0);
    vz[(ro0 + 1 + 16) * 16 + c4] = max4(max4(cen1, vm1), vp1);
    if (tid < 32)
        vz[hrow] = max4(max4(hcen, hdm), hdp);
    __syncthreads();

    #pragma unroll
    for (int q = 0; q < 2; q++) {
        const int ro = ro0 + q * 16;

        float4 hm = max4(max4(vz[ro * 16 + c4], vz[(ro + 1) * 16 + c4]),
                         vz[(ro + 2) * 16 + c4]);

        float lf = __shfl_up_sync(0xffffffffu, hm.w, 1);
        float rt = __shfl_down_sync(0xffffffffu, hm.x, 1);
        if (c4 == 0)  lf = hm.x;
        if (c4 == 15) rt = hm.w;

        float4 m;
        m.x = fmaxf(lf,   fmaxf(hm.x, hm.y));
        m.y = fmaxf(hm.x, fmaxf(hm.y, hm.z));
        m.z = fmaxf(hm.y, fmaxf(hm.z, hm.w));
        m.w = fmaxf(hm.z, fmaxf(hm.w, rt));

        const float4 cen = q ? cen1 : cen0;
        const float4 pp  = q ? pp1  : pp0;
        const float4 cc  = q ? cc1  : cc0;

        float4 nv;
        nv.x = fmaxf(cen.x, fmaf(pp.x, m.x, cc.x));
        nv.y = fmaxf(cen.y, fmaf(pp.y, m.y, cc.y));
        nv.z = fmaxf(cen.z, fmaf(pp.z, m.z, cc.z));
        nv.w = fmaxf(cen.w, fmaf(pp.w, m.w, cc.w));

        vout[q ? off1 : off0] = skip ? cen : nv;
    }
}

// ---------------------------------------------------------------------------
extern "C" void kernel_launch(void* const* d_in, const int* in_sizes, int n_in,
                              void* d_out, int out_size)
{
    const float* image = (const float*)d_in[0];
    const float* hw    = (const float*)d_in[1];
    const float* hb    = (const float*)d_in[2];
    const float* pw    = (const float*)d_in[3];
    const int*   kptr  = (const int*)d_in[4];
    float* out = (float*)d_out;

    void* pv = nullptr;
    cudaGetSymbolAddress(&pv, g_v);
    float* vbuf = (float*)pv;

    conv_mma_kernel<<<dim3(64, 8, 4), 256>>>(image, hw, hb, pw, out);

    const float* src = out;
    float* dst = vbuf;
    for (int i = 0; i < 30; i++) {
        iter_kernel<<<Bn * Dn * 2, 256>>>((const float4*)src, (float4*)dst, kptr, i);
        float* t = dst; dst = (float*)src; src = t;
    }
    // 30 iterations (even count): final write lands in d_out.
}

// round 15
// speedup vs baseline: 1.9003x; 1.6108x over previous
#include <cuda_runtime.h>
#include <math.h>
#include <stdint.h>

#define Bn 4
#define Dn 64
#define Hn 64
#define Wn 64
#define PLANE 4096
#define VOL   262144
#define VOX   1048576

typedef unsigned long long ull;

__device__ float g_p[VOX];
__device__ float g_c[VOX];   // r * (1 - p)
__device__ float g_v[VOX];   // ping-pong buffer

// ---------------- helpers ----------------
__device__ __forceinline__ float4 max4(float4 a, float4 b) {
    return make_float4(fmaxf(a.x, b.x), fmaxf(a.y, b.y),
                       fmaxf(a.z, b.z), fmaxf(a.w, b.w));
}
__device__ __forceinline__ uint32_t cvt_tf32(float x) {
    uint32_t r; asm("cvt.rna.tf32.f32 %0, %1;" : "=r"(r) : "f"(x)); return r;
}
// warp-level tf32 MMA (base ISA, compiles for sm_103)
__device__ __forceinline__ void mma_tf32(float& c0, float& c1, float& c2, float& c3,
                                         const uint32_t a[4], const uint32_t b[2]) {
    asm volatile(
        "mma.sync.aligned.m16n8k8.row.col.f32.tf32.tf32.f32 "
        "{%0,%1,%2,%3}, {%4,%5,%6,%7}, {%8,%9}, {%0,%1,%2,%3};"
        : "+f"(c0), "+f"(c1), "+f"(c2), "+f"(c3)
        : "r"(a[0]), "r"(a[1]), "r"(a[2]), "r"(a[3]), "r"(b[0]), "r"(b[1]));
}

// ---------------------------------------------------------------------------
// Kernel 1: tf32 mma.sync implicit-GEMM conv, nt-outer restructure.
// Block = 256 thr (8 warps) = one d-slice x 8 h-rows; warp = one h-row (64 w)
// = 4 M-tiles of 16 positions, A-fragments for ALL 4 tiles held in regs.
// nt outer loop: each B-fragment load feeds 16 MMAs (was 4).  ch pad 152.
// Epilogue: z = sum pw*relu(d+b); p = sigmoid(z); writes g_p, g_c, v0.
// ---------------------------------------------------------------------------
#define XH  10
#define XRW 68
#define BSTR 17   // B row stride in float2 (16 used + 1 pad)
#define NCH 152
#define NT  19

__global__ __launch_bounds__(256) void conv_mma_kernel(
    const float* __restrict__ image, const float* __restrict__ hw,
    const float* __restrict__ hb,    const float* __restrict__ pw,
    float* __restrict__ vout)
{
    __shared__ float  xs[3 * XH * XRW];     // 8160 B
    __shared__ float2 B2[NCH * BSTR];       // 20672 B: (tap, tap+4) tf32 pairs
    __shared__ float2 wb[NCH];              // (pw, hb)

    const int tid  = threadIdx.x;
    const int warp = tid >> 5;
    const int lane = tid & 31;
    const int d0 = blockIdx.x;
    const int h0 = blockIdx.y * 8;
    const int b  = blockIdx.z;

    // ---- weights: B2[ch][kk*4+j] = tf32(w[ch][kk*8+j], w[ch][kk*8+j+4]) ----
    for (int i = tid; i < NCH * 16; i += 256) {
        const int ch = i >> 4, kp = i & 15;
        const int kk = kp >> 2, j = kp & 3;
        const int t0 = kk * 8 + j, t1 = t0 + 4;
        const float w0 = (ch < 150 && t0 < 27) ? hw[ch * 27 + t0] : 0.f;
        const float w1 = (ch < 150 && t1 < 27) ? hw[ch * 27 + t1] : 0.f;
        B2[ch * BSTR + kp] = make_float2(__uint_as_float(cvt_tf32(w0)),
                                         __uint_as_float(cvt_tf32(w1)));
    }
    for (int i = tid; i < NCH; i += 256)
        wb[i] = (i < 150) ? make_float2(pw[i], hb[i]) : make_float2(0.f, 0.f);

    // ---- x halo tile: planes d0-1..d0+1, rows h0-1..h0+8, cols -1..64 ----
    const float* xg = image + (size_t)b * 2 * VOL;
    const float* rg = xg + VOL;
    for (int i = tid; i < 3 * XH * 66; i += 256) {
        const int wl = i % 66; const int rest = i / 66;
        const int rl = rest % XH; const int dz = rest / XH;
        const int gw = wl - 1, gh = h0 + rl - 1, gd = d0 + dz - 1;
        float v = 0.f;
        if (gw >= 0 && gw < Wn && gh >= 0 && gh < Hn && gd >= 0 && gd < Dn)
            v = xg[((size_t)gd * Hn + gh) * Wn + gw];
        xs[(dz * XH + rl) * XRW + wl] = v;
    }
    __syncthreads();

    const int g   = lane >> 2;     // 0..7
    const int tig = lane & 3;      // 0..3
    const int hl  = warp;          // this warp's h row

    // ---- gather A fragments for ALL 4 M-tiles x 4 k-steps (64 regs) ----
    uint32_t afr[4][4][4];
    #pragma unroll
    for (int mt = 0; mt < 4; mt++)
        #pragma unroll
        for (int kk = 0; kk < 4; kk++)
            #pragma unroll
            for (int hh = 0; hh < 2; hh++) {
                const int t = kk * 8 + tig + hh * 4;
                uint32_t lo = 0u, hi = 0u;
                if (t < 27) {
                    const int dz = t / 9, rem = t - dz * 9;
                    const int hy = rem / 3, kx = rem - hy * 3;
                    const float* rp = &xs[(dz * XH + hl + hy) * XRW + mt * 16 + g + kx];
                    lo = cvt_tf32(rp[0]);           // A row g
                    hi = cvt_tf32(rp[8]);           // A row g+8
                }
                afr[mt][kk][hh * 2 + 0] = lo;
                afr[mt][kk][hh * 2 + 1] = hi;
            }

    float zz[4][2];
    #pragma unroll
    for (int mt = 0; mt < 4; mt++) { zz[mt][0] = 0.f; zz[mt][1] = 0.f; }

    #pragma unroll 1
    for (int nt = 0; nt < NT; nt++) {
        // B fragments: ch = nt*8 + g (one load set feeds all 4 M-tiles)
        uint32_t bfr[4][2];
        const float2* bp = &B2[(nt * 8 + g) * BSTR + tig];
        #pragma unroll
        for (int kk = 0; kk < 4; kk++) {
            const float2 bb = bp[kk * 4];
            bfr[kk][0] = __float_as_uint(bb.x);
            bfr[kk][1] = __float_as_uint(bb.y);
        }
        const float4 wq = *(const float4*)&wb[nt * 8 + 2 * tig]; // pw0,b0,pw1,b1

        #pragma unroll
        for (int mt = 0; mt < 4; mt++) {
            float c0 = 0.f, c1 = 0.f, c2 = 0.f, c3 = 0.f;
            #pragma unroll
            for (int kk = 0; kk < 4; kk++)
                mma_tf32(c0, c1, c2, c3, afr[mt][kk], bfr[kk]);

            zz[mt][0] = fmaf(wq.x, fmaxf(c0 + wq.y, 0.f),
                        fmaf(wq.z, fmaxf(c1 + wq.w, 0.f), zz[mt][0]));
            zz[mt][1] = fmaf(wq.x, fmaxf(c2 + wq.y, 0.f),
                        fmaf(wq.z, fmaxf(c3 + wq.w, 0.f), zz[mt][1]));
        }
    }

    // ---- reduce + write out ----
    #pragma unroll
    for (int mt = 0; mt < 4; mt++) {
        float z0 = zz[mt][0], z1 = zz[mt][1];
        z0 += __shfl_xor_sync(0xffffffffu, z0, 1);
        z0 += __shfl_xor_sync(0xffffffffu, z0, 2);
        z1 += __shfl_xor_sync(0xffffffffu, z1, 1);
        z1 += __shfl_xor_sync(0xffffffffu, z1, 2);

        if (tig < 2) {
            const int w  = mt * 16 + g + (tig == 1 ? 8 : 0);
            const float z = (tig == 1) ? z1 : z0;
            const int gh = h0 + hl;
            const size_t o = ((size_t)b * Dn + d0) * PLANE + gh * Wn + w;
            const float r = rg[((size_t)d0 * Hn + gh) * Wn + w];
            const float p = 1.f / (1.f + __expf(-z));
            g_p[o]  = p;
            g_c[o]  = r * (1.f - p);
            vout[o] = r;
        }
    }
}

// ---------------------------------------------------------------------------
// Kernel 2 (proven R11): one propagation iteration, 32-row half-planes,
// all independent global loads issued up front.
// ---------------------------------------------------------------------------
__global__ __launch_bounds__(256) void iter_kernel(
    const float4* __restrict__ vin, float4* __restrict__ vout,
    const int* __restrict__ kptr, int it)
{
    __shared__ float4 vz[34 * 16];

    const int blk = blockIdx.x;
    const int bd  = blk >> 1;
    const int h0  = (blk & 1) * 32;
    const int d   = bd & 63;
    const int tid = threadIdx.x;
    const bool skip = (it >= *kptr);

    const size_t base = (size_t)bd * 1024;
    const long long dm = (d > 0)  ? -1024 : 0;
    const long long dp = (d < 63) ?  1024 : 0;

    const int ro0 = tid >> 4;
    const int c4  = tid & 15;
    const size_t off0 = base + (h0 + ro0) * 16 + c4;
    const size_t off1 = off0 + 16 * 16;

    float4 cen0 = vin[off0],      cen1 = vin[off1];
    float4 vm0  = vin[off0 + dm], vm1  = vin[off1 + dm];
    float4 vp0  = vin[off0 + dp], vp1  = vin[off1 + dp];
    const float4 pp0 = ((const float4*)g_p)[off0];
    const float4 pp1 = ((const float4*)g_p)[off1];
    const float4 cc0 = ((const float4*)g_c)[off0];
    const float4 cc1 = ((const float4*)g_c)[off1];

    float4 hcen, hdm, hdp;
    int hrow = 0;
    if (tid < 32) {
        const int hc4 = tid & 15;
        const int hr  = (tid < 16) ? -1 : 32;
        const int gh  = min(63, max(0, h0 + hr));
        const size_t hoff = base + gh * 16 + hc4;
        hcen = vin[hoff];
        hdm  = vin[hoff + dm];
        hdp  = vin[hoff + dp];
        hrow = (hr + 1) * 16 + hc4;
    }

    vz[(ro0 + 1) * 16 + c4]      = max4(max4(cen0, vm0), vp0);
    vz[(ro0 + 1 + 16) * 16 + c4] = max4(max4(cen1, vm1), vp1);
    if (tid < 32)
        vz[hrow] = max4(max4(hcen, hdm), hdp);
    __syncthreads();

    #pragma unroll
    for (int q = 0; q < 2; q++) {
        const int ro = ro0 + q * 16;

        float4 hm = max4(max4(vz[ro * 16 + c4], vz[(ro + 1) * 16 + c4]),
                         vz[(ro + 2) * 16 + c4]);

        float lf = __shfl_up_sync(0xffffffffu, hm.w, 1);
        float rt = __shfl_down_sync(0xffffffffu, hm.x, 1);
        if (c4 == 0)  lf = hm.x;
        if (c4 == 15) rt = hm.w;

        float4 m;
        m.x = fmaxf(lf,   fmaxf(hm.x, hm.y));
        m.y = fmaxf(hm.x, fmaxf(hm.y, hm.z));
        m.z = fmaxf(hm.y, fmaxf(hm.z, hm.w));
        m.w = fmaxf(hm.z, fmaxf(hm.w, rt));

        const float4 cen = q ? cen1 : cen0;
        const float4 pp  = q ? pp1  : pp0;
        const float4 cc  = q ? cc1  : cc0;

        float4 nv;
        nv.x = fmaxf(cen.x, fmaf(pp.x, m.x, cc.x));
        nv.y = fmaxf(cen.y, fmaf(pp.y, m.y, cc.y));
        nv.z = fmaxf(cen.z, fmaf(pp.z, m.z, cc.z));
        nv.w = fmaxf(cen.w, fmaf(pp.w, m.w, cc.w));

        vout[q ? off1 : off0] = skip ? cen : nv;
    }
}

// ---------------------------------------------------------------------------
extern "C" void kernel_launch(void* const* d_in, const int* in_sizes, int n_in,
                              void* d_out, int out_size)
{
    const float* image = (const float*)d_in[0];
    const float* hw    = (const float*)d_in[1];
    const float* hb    = (const float*)d_in[2];
    const float* pw    = (const float*)d_in[3];
    const int*   kptr  = (const int*)d_in[4];
    float* out = (float*)d_out;

    void* pv = nullptr;
    cudaGetSymbolAddress(&pv, g_v);
    float* vbuf = (float*)pv;

    conv_mma_kernel<<<dim3(64, 8, 4), 256>>>(image, hw, hb, pw, out);

    const float* src = out;
    float* dst = vbuf;
    for (int i = 0; i < 30; i++) {
        iter_kernel<<<Bn * Dn * 2, 256>>>((const float4*)src, (float4*)dst, kptr, i);
        float* t = dst; dst = (float*)src; src = t;
    }
    // 30 iterations (even count): final write lands in d_out.
}